// round 8
// baseline (speedup 1.0000x reference)
#include <cuda_runtime.h>
#include <cstdint>

#define D 128
#define MAXN 50000
#define MAXE 800000

// ---------------- scratch (no allocations allowed) ----------------
__device__ float g_agg[MAXN * D];     // mean-aggregated features
__device__ float g_h[MAXN * D];       // pre-BN GEMM output
__device__ float g_h1[MAXN * D];      // post BN+ReLU layer-1 output
__device__ float g_stats[4 * D];      // [colsum | colsumsq | scale | shift]
__device__ float g_wt[2 * 256 * 128]; // tf32 weights per layer, [layer][k=256][n=128]
__device__ int   g_cnt[MAXN];         // per-dst edge count
__device__ int   g_off[MAXN + 1];     // CSR offsets
__device__ int   g_cursor[MAXN];      // fill cursors
__device__ int   g_csr[MAXE];         // CSR src lists

__device__ __forceinline__ float to_tf32(float x) {
    uint32_t u;
    asm("cvt.rna.tf32.f32 %0, %1;" : "=r"(u) : "f"(x));
    return __uint_as_float(u);
}

// ---------------- CSR build (once; graph shared by both layers) ----------------
__global__ void zero_cnt_kernel(int N) {
    int i = blockIdx.x * blockDim.x + threadIdx.x;
    if (i < N) g_cnt[i] = 0;
}
__global__ void count_kernel(const int* __restrict__ ei, int E) {
    int e = blockIdx.x * blockDim.x + threadIdx.x;
    if (e < E) atomicAdd(&g_cnt[ei[E + e]], 1);
}
// single-block exclusive scan over g_cnt -> g_off (+ cursor copy)
__global__ void scan_kernel(int N, int E) {
    __shared__ int ps[1024];
    int t = threadIdx.x;
    int C = (N + 1023) / 1024;
    int base = t * C;
    int sum = 0;
    for (int i = 0; i < C; i++) {
        int idx = base + i;
        if (idx < N) sum += g_cnt[idx];
    }
    ps[t] = sum;
    __syncthreads();
    for (int off = 1; off < 1024; off <<= 1) {
        int v = (t >= off) ? ps[t - off] : 0;
        __syncthreads();
        if (t >= off) ps[t] += v;
        __syncthreads();
    }
    int run = (t > 0) ? ps[t - 1] : 0;
    for (int i = 0; i < C; i++) {
        int idx = base + i;
        if (idx < N) {
            g_off[idx] = run;
            g_cursor[idx] = run;
            run += g_cnt[idx];
        }
    }
    if (t == 1023) g_off[N] = E;
}
__global__ void fill_kernel(const int* __restrict__ ei, int E) {
    int e = blockIdx.x * blockDim.x + threadIdx.x;
    if (e >= E) return;
    int s = ei[e];
    int d = ei[E + e];
    int pos = atomicAdd(&g_cursor[d], 1);
    g_csr[pos] = s;
}

// ---------------- weights -> tf32, [k][n] layout (both layers, once) ----------------
__global__ void wt_kernel(const float* __restrict__ W1l, const float* __restrict__ W1r,
                          const float* __restrict__ W2l, const float* __restrict__ W2r) {
    int i = blockIdx.x * blockDim.x + threadIdx.x;
    if (i >= 256 * 128) return;
    int k = i >> 7;
    int n = i & 127;
    float v1 = (k < 128) ? W1l[k * 128 + n] : W1r[(k - 128) * 128 + n];
    float v2 = (k < 128) ? W2l[k * 128 + n] : W2r[(k - 128) * 128 + n];
    g_wt[i] = to_tf32(v1);
    g_wt[256 * 128 + i] = to_tf32(v2);
}

__global__ void zero_stats_kernel() {
    int i = threadIdx.x;
    if (i < 2 * D) g_stats[i] = 0.f;
}

// ---------------- gather-mean: one warp per dst node, no atomics ----------------
__global__ void gather_mean_kernel(const float* __restrict__ xext, int useInternal, int N) {
    const float* feat = useInternal ? g_h1 : xext;
    int gtid = blockIdx.x * blockDim.x + threadIdx.x;
    int w = gtid >> 5;
    int lane = gtid & 31;
    if (w >= N) return;
    int beg = g_off[w];
    int end = g_off[w + 1];
    float4 acc = make_float4(0.f, 0.f, 0.f, 0.f);
    int j = beg;
    for (; j + 4 <= end; j += 4) {
        int s0 = __ldg(&g_csr[j + 0]);
        int s1 = __ldg(&g_csr[j + 1]);
        int s2 = __ldg(&g_csr[j + 2]);
        int s3 = __ldg(&g_csr[j + 3]);
        float4 v0 = ((const float4*)(feat + (size_t)s0 * D))[lane];
        float4 v1 = ((const float4*)(feat + (size_t)s1 * D))[lane];
        float4 v2 = ((const float4*)(feat + (size_t)s2 * D))[lane];
        float4 v3 = ((const float4*)(feat + (size_t)s3 * D))[lane];
        acc.x += v0.x + v1.x + v2.x + v3.x;
        acc.y += v0.y + v1.y + v2.y + v3.y;
        acc.z += v0.z + v1.z + v2.z + v3.z;
        acc.w += v0.w + v1.w + v2.w + v3.w;
    }
    for (; j < end; j++) {
        int s = __ldg(&g_csr[j]);
        float4 v = ((const float4*)(feat + (size_t)s * D))[lane];
        acc.x += v.x; acc.y += v.y; acc.z += v.z; acc.w += v.w;
    }
    float sc = 1.f / (float)max(end - beg, 1);
    acc.x *= sc; acc.y *= sc; acc.z *= sc; acc.w *= sc;
    ((float4*)(g_agg + (size_t)w * D))[lane] = acc;
}

// ---------------- mma.sync tf32 GEMM: h = agg@Wl + x@Wr + b (+ col stats) ----------------
// CTA: 128 rows x 128 cols. 256 threads = 8 warps (4 along M x 2 along N).
__global__ __launch_bounds__(256) void gemm_mma(
    const float* __restrict__ xext, int useInternal, int layer,
    const float* __restrict__ bias, int M)
{
    const float* xin = useInternal ? g_h1 : xext;
    const float* wt = g_wt + (size_t)layer * (256 * 128);
    __shared__ float As[128][36];
    __shared__ float Bs[32][136];
    __shared__ float sbias[128];
    __shared__ float ss[128], sq[128];

    int tid = threadIdx.x;
    int lane = tid & 31;
    int wid = tid >> 5;
    int warpM = wid & 3;
    int warpN = wid >> 2;
    int row0 = blockIdx.x * 128;

    if (tid < 128) {
        sbias[tid] = bias[tid];
        ss[tid] = 0.f;
        sq[tid] = 0.f;
    }

    float acc[2][8][4];
#pragma unroll
    for (int ma = 0; ma < 2; ma++)
#pragma unroll
        for (int na = 0; na < 8; na++)
#pragma unroll
            for (int j = 0; j < 4; j++) acc[ma][na][j] = 0.f;

    for (int c = 0; c < 8; c++) {
        int k0 = c * 32;
        const float* Asrc = (k0 < 128) ? g_agg : xin;
        int koff = k0 & 127;
        __syncthreads();
#pragma unroll
        for (int i = 0; i < 4; i++) {
            int idx = tid + i * 256;
            int r = idx >> 3;
            int cc = (idx & 7) * 4;
            int gr = row0 + r;
            float4 v = make_float4(0.f, 0.f, 0.f, 0.f);
            if (gr < M) v = *(const float4*)&Asrc[(size_t)gr * D + koff + cc];
            v.x = to_tf32(v.x); v.y = to_tf32(v.y); v.z = to_tf32(v.z); v.w = to_tf32(v.w);
            *(float4*)&As[r][cc] = v;
        }
#pragma unroll
        for (int i = 0; i < 4; i++) {
            int idx = tid + i * 256;
            int k = idx >> 5;
            int nn = (idx & 31) * 4;
            *(float4*)&Bs[k][nn] = *(const float4*)&wt[(size_t)(k0 + k) * 128 + nn];
        }
        __syncthreads();
#pragma unroll
        for (int kk = 0; kk < 32; kk += 8) {
            uint32_t a[2][4];
            int ar = warpM * 32 + (lane >> 2);
            int ac = kk + (lane & 3);
#pragma unroll
            for (int ma = 0; ma < 2; ma++) {
                int r = ar + ma * 16;
                a[ma][0] = __float_as_uint(As[r][ac]);
                a[ma][1] = __float_as_uint(As[r + 8][ac]);
                a[ma][2] = __float_as_uint(As[r][ac + 4]);
                a[ma][3] = __float_as_uint(As[r + 8][ac + 4]);
            }
#pragma unroll
            for (int na = 0; na < 8; na++) {
                int bn = warpN * 64 + na * 8 + (lane >> 2);
                int bk = kk + (lane & 3);
                uint32_t b0 = __float_as_uint(Bs[bk][bn]);
                uint32_t b1 = __float_as_uint(Bs[bk + 4][bn]);
#pragma unroll
                for (int ma = 0; ma < 2; ma++) {
                    asm volatile(
                        "mma.sync.aligned.m16n8k8.row.col.f32.tf32.tf32.f32 "
                        "{%0,%1,%2,%3}, {%4,%5,%6,%7}, {%8,%9}, {%0,%1,%2,%3};"
                        : "+f"(acc[ma][na][0]), "+f"(acc[ma][na][1]),
                          "+f"(acc[ma][na][2]), "+f"(acc[ma][na][3])
                        : "r"(a[ma][0]), "r"(a[ma][1]), "r"(a[ma][2]), "r"(a[ma][3]),
                          "r"(b0), "r"(b1));
                }
            }
        }
    }

    // epilogue: +bias, store h, accumulate column stats
    int r0 = row0 + warpM * 32 + (lane >> 2);
    int c0 = warpN * 64 + 2 * (lane & 3);
#pragma unroll
    for (int na = 0; na < 8; na++) {
        int col = c0 + na * 8;
        float s0 = 0.f, s1 = 0.f, q0 = 0.f, q1 = 0.f;
#pragma unroll
        for (int ma = 0; ma < 2; ma++) {
            int gr = r0 + ma * 16;
            if (gr < M) {
                float o0 = acc[ma][na][0] + sbias[col];
                float o1 = acc[ma][na][1] + sbias[col + 1];
                *(float2*)&g_h[(size_t)gr * D + col] = make_float2(o0, o1);
                s0 += o0; s1 += o1; q0 += o0 * o0; q1 += o1 * o1;
            }
            if (gr + 8 < M) {
                float o0 = acc[ma][na][2] + sbias[col];
                float o1 = acc[ma][na][3] + sbias[col + 1];
                *(float2*)&g_h[(size_t)(gr + 8) * D + col] = make_float2(o0, o1);
                s0 += o0; s1 += o1; q0 += o0 * o0; q1 += o1 * o1;
            }
        }
        atomicAdd(&ss[col], s0);
        atomicAdd(&ss[col + 1], s1);
        atomicAdd(&sq[col], q0);
        atomicAdd(&sq[col + 1], q1);
    }
    __syncthreads();
    if (tid < 128) {
        atomicAdd(&g_stats[tid], ss[tid]);
        atomicAdd(&g_stats[D + tid], sq[tid]);
    }
}

// ---------------- BN params -> scale/shift ----------------
__global__ void stats_kernel(const float* __restrict__ gamma,
                             const float* __restrict__ beta, int M) {
    int c = threadIdx.x;
    float inv = 1.f / (float)M;
    float mean = g_stats[c] * inv;
    float var = g_stats[D + c] * inv - mean * mean;
    float sc = gamma[c] * rsqrtf(var + 1e-5f);
    g_stats[2 * D + c] = sc;
    g_stats[3 * D + c] = beta[c] - mean * sc;
}

// ---------------- apply BN + ReLU (layer 1) ----------------
__global__ void apply_relu_kernel(int M) {
    int i = blockIdx.x * blockDim.x + threadIdx.x;
    if (i >= M * (D / 4)) return;
    int c4 = i & (D / 4 - 1);
    float4 v = ((const float4*)g_h)[i];
    float4 sc = *(const float4*)&g_stats[2 * D + c4 * 4];
    float4 sh = *(const float4*)&g_stats[3 * D + c4 * 4];
    float4 o;
    o.x = fmaxf(fmaf(v.x, sc.x, sh.x), 0.f);
    o.y = fmaxf(fmaf(v.y, sc.y, sh.y), 0.f);
    o.z = fmaxf(fmaf(v.z, sc.z, sh.z), 0.f);
    o.w = fmaxf(fmaf(v.w, sc.w, sh.w), 0.f);
    ((float4*)g_h1)[i] = o;
}

// ---------------- apply BN + residual + ReLU (layer 2) ----------------
__global__ void final_kernel(const float* __restrict__ xin, float* __restrict__ out, int M) {
    int i = blockIdx.x * blockDim.x + threadIdx.x;
    if (i >= M * (D / 4)) return;
    int c4 = i & (D / 4 - 1);
    float4 v = ((const float4*)g_h)[i];
    float4 xv = ((const float4*)xin)[i];
    float4 sc = *(const float4*)&g_stats[2 * D + c4 * 4];
    float4 sh = *(const float4*)&g_stats[3 * D + c4 * 4];
    float4 o;
    o.x = fmaxf(fmaf(v.x, sc.x, sh.x) + xv.x, 0.f);
    o.y = fmaxf(fmaf(v.y, sc.y, sh.y) + xv.y, 0.f);
    o.z = fmaxf(fmaf(v.z, sc.z, sh.z) + xv.z, 0.f);
    o.w = fmaxf(fmaf(v.w, sc.w, sh.w) + xv.w, 0.f);
    ((float4*)out)[i] = o;
}

extern "C" void kernel_launch(void* const* d_in, const int* in_sizes, int n_in,
                              void* d_out, int out_size) {
    const float* x       = (const float*)d_in[0];
    const int*   ei      = (const int*)d_in[1];   // int32 edge_index
    const float* W1l     = (const float*)d_in[2];
    const float* b1      = (const float*)d_in[3];
    const float* W1r     = (const float*)d_in[4];
    const float* g1      = (const float*)d_in[5];
    const float* bt1     = (const float*)d_in[6];
    const float* W2l     = (const float*)d_in[7];
    const float* b2      = (const float*)d_in[8];
    const float* W2r     = (const float*)d_in[9];
    const float* g2      = (const float*)d_in[10];
    const float* bt2     = (const float*)d_in[11];
    float* out = (float*)d_out;

    int M = in_sizes[0] / D;
    int E = in_sizes[1] / 2;
    int eb = (E + 255) / 256;
    int nb = (M + 255) / 256;
    int gather_blocks = (M + 7) / 8;          // 8 warps (nodes) per block
    int gemm_blocks = (M + 127) / 128;
    int ew_blocks = (M * (D / 4) + 255) / 256;

    // ---- CSR build (once) + weight conversion ----
    zero_cnt_kernel<<<nb, 256>>>(M);
    wt_kernel<<<128, 256>>>(W1l, W1r, W2l, W2r);
    count_kernel<<<eb, 256>>>(ei, E);
    scan_kernel<<<1, 1024>>>(M, E);
    fill_kernel<<<eb, 256>>>(ei, E);

    // ---- layer 1 ----
    zero_stats_kernel<<<1, 256>>>();
    gather_mean_kernel<<<gather_blocks, 256>>>(x, 0, M);
    gemm_mma<<<gemm_blocks, 256>>>(x, 0, 0, b1, M);
    stats_kernel<<<1, D>>>(g1, bt1, M);
    apply_relu_kernel<<<ew_blocks, 256>>>(M);

    // ---- layer 2 ----
    zero_stats_kernel<<<1, 256>>>();
    gather_mean_kernel<<<gather_blocks, 256>>>(nullptr, 1, M);
    gemm_mma<<<gemm_blocks, 256>>>(nullptr, 1, 1, b2, M);
    stats_kernel<<<1, D>>>(g2, bt2, M);
    final_kernel<<<ew_blocks, 256>>>(x, out, M);
}

// round 9
// speedup vs baseline: 1.2449x; 1.2449x over previous
#include <cuda_runtime.h>
#include <cstdint>

#define D 128
#define MAXN 50000
#define MAXE 800000
#define SCAN_TILE 1024

// ---------------- scratch (no allocations allowed) ----------------
__device__ float g_agg[MAXN * D];     // mean-aggregated features
__device__ float g_h[MAXN * D];       // pre-BN GEMM output
__device__ float g_h1[MAXN * D];      // post BN+ReLU layer-1 output
__device__ float g_stats[4 * D];      // [colsum | colsumsq | scale | shift]
__device__ float g_wt[2 * 256 * 128]; // tf32 weights per layer, [layer][k=256][n=128]
__device__ int   g_cnt[MAXN];         // per-dst edge count
__device__ int   g_off[MAXN + 1];     // CSR offsets
__device__ int   g_cursor[MAXN];      // fill cursors
__device__ int   g_csr[MAXE];         // CSR src lists
__device__ int   g_bsum[64];          // per-tile sums
__device__ int   g_boff[64];          // per-tile exclusive offsets

__device__ __forceinline__ float to_tf32(float x) {
    uint32_t u;
    asm("cvt.rna.tf32.f32 %0, %1;" : "=r"(u) : "f"(x));
    return __uint_as_float(u);
}

// ---------------- CSR build (once; graph shared by both layers) ----------------
__global__ void zero_cnt_kernel(int N) {
    int i = blockIdx.x * blockDim.x + threadIdx.x;
    if (i < N) g_cnt[i] = 0;
}
__global__ void count_kernel(const int* __restrict__ ei, int E) {
    int e = blockIdx.x * blockDim.x + threadIdx.x;
    if (e < E) atomicAdd(&g_cnt[ei[E + e]], 1);
}
// level 1: per-tile (1024 elems) sums, coalesced
__global__ void tile_sum_kernel(int N) {
    __shared__ int sh[256];
    int b = blockIdx.x;
    int t = threadIdx.x;
    int base = b * SCAN_TILE;
    int v = 0;
#pragma unroll
    for (int i = 0; i < 4; i++) {
        int idx = base + t + i * 256;
        if (idx < N) v += g_cnt[idx];
    }
    sh[t] = v;
    __syncthreads();
    for (int off = 128; off > 0; off >>= 1) {
        if (t < off) sh[t] += sh[t + off];
        __syncthreads();
    }
    if (t == 0) g_bsum[b] = sh[0];
}
// level 2: scan tile sums (<=64 tiles) in one warp-ish block
__global__ void tile_scan_kernel(int nt, int N, int E) {
    __shared__ int sh[64];
    int t = threadIdx.x;
    sh[t] = (t < nt) ? g_bsum[t] : 0;
    __syncthreads();
    for (int off = 1; off < 64; off <<= 1) {
        int v = (t >= off) ? sh[t - off] : 0;
        __syncthreads();
        sh[t] += v;
        __syncthreads();
    }
    if (t < nt) g_boff[t] = sh[t] - g_bsum[t];   // exclusive
    if (t == 0) g_off[N] = E;
}
// level 3: local scan within each tile + tile base -> g_off/g_cursor
__global__ void local_scan_kernel(int N) {
    __shared__ int sh[SCAN_TILE];
    int b = blockIdx.x;
    int t = threadIdx.x;
    int idx = b * SCAN_TILE + t;
    int v = (idx < N) ? g_cnt[idx] : 0;
    sh[t] = v;
    __syncthreads();
    for (int off = 1; off < SCAN_TILE; off <<= 1) {
        int u = (t >= off) ? sh[t - off] : 0;
        __syncthreads();
        sh[t] += u;
        __syncthreads();
    }
    if (idx < N) {
        int excl = g_boff[b] + sh[t] - v;
        g_off[idx] = excl;
        g_cursor[idx] = excl;
    }
}
__global__ void fill_kernel(const int* __restrict__ ei, int E) {
    int e = blockIdx.x * blockDim.x + threadIdx.x;
    if (e >= E) return;
    int s = ei[e];
    int d = ei[E + e];
    int pos = atomicAdd(&g_cursor[d], 1);
    g_csr[pos] = s;
}

// ---------------- weights -> tf32, [k][n] layout (both layers, once) ----------------
__global__ void wt_kernel(const float* __restrict__ W1l, const float* __restrict__ W1r,
                          const float* __restrict__ W2l, const float* __restrict__ W2r) {
    int i = blockIdx.x * blockDim.x + threadIdx.x;
    if (i >= 256 * 128) return;
    int k = i >> 7;
    int n = i & 127;
    float v1 = (k < 128) ? W1l[k * 128 + n] : W1r[(k - 128) * 128 + n];
    float v2 = (k < 128) ? W2l[k * 128 + n] : W2r[(k - 128) * 128 + n];
    g_wt[i] = to_tf32(v1);
    g_wt[256 * 128 + i] = to_tf32(v2);
}

__global__ void zero_stats_kernel() {
    int i = threadIdx.x;
    if (i < 2 * D) g_stats[i] = 0.f;
}

// ---------------- gather-mean: one warp per dst node, no atomics ----------------
__global__ void gather_mean_kernel(const float* __restrict__ xext, int useInternal, int N) {
    const float* feat = useInternal ? g_h1 : xext;
    int gtid = blockIdx.x * blockDim.x + threadIdx.x;
    int w = gtid >> 5;
    int lane = gtid & 31;
    if (w >= N) return;
    int beg = g_off[w];
    int end = g_off[w + 1];
    float4 acc = make_float4(0.f, 0.f, 0.f, 0.f);
    int j = beg;
    for (; j + 4 <= end; j += 4) {
        int s0 = __ldg(&g_csr[j + 0]);
        int s1 = __ldg(&g_csr[j + 1]);
        int s2 = __ldg(&g_csr[j + 2]);
        int s3 = __ldg(&g_csr[j + 3]);
        float4 v0 = ((const float4*)(feat + (size_t)s0 * D))[lane];
        float4 v1 = ((const float4*)(feat + (size_t)s1 * D))[lane];
        float4 v2 = ((const float4*)(feat + (size_t)s2 * D))[lane];
        float4 v3 = ((const float4*)(feat + (size_t)s3 * D))[lane];
        acc.x += v0.x + v1.x + v2.x + v3.x;
        acc.y += v0.y + v1.y + v2.y + v3.y;
        acc.z += v0.z + v1.z + v2.z + v3.z;
        acc.w += v0.w + v1.w + v2.w + v3.w;
    }
    for (; j < end; j++) {
        int s = __ldg(&g_csr[j]);
        float4 v = ((const float4*)(feat + (size_t)s * D))[lane];
        acc.x += v.x; acc.y += v.y; acc.z += v.z; acc.w += v.w;
    }
    float sc = 1.f / (float)max(end - beg, 1);
    acc.x *= sc; acc.y *= sc; acc.z *= sc; acc.w *= sc;
    ((float4*)(g_agg + (size_t)w * D))[lane] = acc;
}

// ---------------- mma.sync tf32 GEMM: h = agg@Wl + x@Wr + b (+ col stats) ----------------
// CTA: 128 rows x 128 cols. 256 threads = 8 warps (4 along M x 2 along N).
__global__ __launch_bounds__(256) void gemm_mma(
    const float* __restrict__ xext, int useInternal, int layer,
    const float* __restrict__ bias, int M)
{
    const float* xin = useInternal ? g_h1 : xext;
    const float* wt = g_wt + (size_t)layer * (256 * 128);
    __shared__ float As[128][36];
    __shared__ float Bs[32][136];
    __shared__ float sbias[128];
    __shared__ float ss[128], sq[128];

    int tid = threadIdx.x;
    int lane = tid & 31;
    int wid = tid >> 5;
    int warpM = wid & 3;
    int warpN = wid >> 2;
    int row0 = blockIdx.x * 128;

    if (tid < 128) {
        sbias[tid] = bias[tid];
        ss[tid] = 0.f;
        sq[tid] = 0.f;
    }

    float acc[2][8][4];
#pragma unroll
    for (int ma = 0; ma < 2; ma++)
#pragma unroll
        for (int na = 0; na < 8; na++)
#pragma unroll
            for (int j = 0; j < 4; j++) acc[ma][na][j] = 0.f;

    for (int c = 0; c < 8; c++) {
        int k0 = c * 32;
        const float* Asrc = (k0 < 128) ? g_agg : xin;
        int koff = k0 & 127;
        __syncthreads();
#pragma unroll
        for (int i = 0; i < 4; i++) {
            int idx = tid + i * 256;
            int r = idx >> 3;
            int cc = (idx & 7) * 4;
            int gr = row0 + r;
            float4 v = make_float4(0.f, 0.f, 0.f, 0.f);
            if (gr < M) v = *(const float4*)&Asrc[(size_t)gr * D + koff + cc];
            v.x = to_tf32(v.x); v.y = to_tf32(v.y); v.z = to_tf32(v.z); v.w = to_tf32(v.w);
            *(float4*)&As[r][cc] = v;
        }
#pragma unroll
        for (int i = 0; i < 4; i++) {
            int idx = tid + i * 256;
            int k = idx >> 5;
            int nn = (idx & 31) * 4;
            *(float4*)&Bs[k][nn] = *(const float4*)&wt[(size_t)(k0 + k) * 128 + nn];
        }
        __syncthreads();
#pragma unroll
        for (int kk = 0; kk < 32; kk += 8) {
            uint32_t a[2][4];
            int ar = warpM * 32 + (lane >> 2);
            int ac = kk + (lane & 3);
#pragma unroll
            for (int ma = 0; ma < 2; ma++) {
                int r = ar + ma * 16;
                a[ma][0] = __float_as_uint(As[r][ac]);
                a[ma][1] = __float_as_uint(As[r + 8][ac]);
                a[ma][2] = __float_as_uint(As[r][ac + 4]);
                a[ma][3] = __float_as_uint(As[r + 8][ac + 4]);
            }
#pragma unroll
            for (int na = 0; na < 8; na++) {
                int bn = warpN * 64 + na * 8 + (lane >> 2);
                int bk = kk + (lane & 3);
                uint32_t b0 = __float_as_uint(Bs[bk][bn]);
                uint32_t b1 = __float_as_uint(Bs[bk + 4][bn]);
#pragma unroll
                for (int ma = 0; ma < 2; ma++) {
                    asm volatile(
                        "mma.sync.aligned.m16n8k8.row.col.f32.tf32.tf32.f32 "
                        "{%0,%1,%2,%3}, {%4,%5,%6,%7}, {%8,%9}, {%0,%1,%2,%3};"
                        : "+f"(acc[ma][na][0]), "+f"(acc[ma][na][1]),
                          "+f"(acc[ma][na][2]), "+f"(acc[ma][na][3])
                        : "r"(a[ma][0]), "r"(a[ma][1]), "r"(a[ma][2]), "r"(a[ma][3]),
                          "r"(b0), "r"(b1));
                }
            }
        }
    }

    // epilogue: +bias, store h, accumulate column stats
    int r0 = row0 + warpM * 32 + (lane >> 2);
    int c0 = warpN * 64 + 2 * (lane & 3);
#pragma unroll
    for (int na = 0; na < 8; na++) {
        int col = c0 + na * 8;
        float s0 = 0.f, s1 = 0.f, q0 = 0.f, q1 = 0.f;
#pragma unroll
        for (int ma = 0; ma < 2; ma++) {
            int gr = r0 + ma * 16;
            if (gr < M) {
                float o0 = acc[ma][na][0] + sbias[col];
                float o1 = acc[ma][na][1] + sbias[col + 1];
                *(float2*)&g_h[(size_t)gr * D + col] = make_float2(o0, o1);
                s0 += o0; s1 += o1; q0 += o0 * o0; q1 += o1 * o1;
            }
            if (gr + 8 < M) {
                float o0 = acc[ma][na][2] + sbias[col];
                float o1 = acc[ma][na][3] + sbias[col + 1];
                *(float2*)&g_h[(size_t)(gr + 8) * D + col] = make_float2(o0, o1);
                s0 += o0; s1 += o1; q0 += o0 * o0; q1 += o1 * o1;
            }
        }
        atomicAdd(&ss[col], s0);
        atomicAdd(&ss[col + 1], s1);
        atomicAdd(&sq[col], q0);
        atomicAdd(&sq[col + 1], q1);
    }
    __syncthreads();
    if (tid < 128) {
        atomicAdd(&g_stats[tid], ss[tid]);
        atomicAdd(&g_stats[D + tid], sq[tid]);
    }
}

// ---------------- BN params -> scale/shift ----------------
__global__ void stats_kernel(const float* __restrict__ gamma,
                             const float* __restrict__ beta, int M) {
    int c = threadIdx.x;
    float inv = 1.f / (float)M;
    float mean = g_stats[c] * inv;
    float var = g_stats[D + c] * inv - mean * mean;
    float sc = gamma[c] * rsqrtf(var + 1e-5f);
    g_stats[2 * D + c] = sc;
    g_stats[3 * D + c] = beta[c] - mean * sc;
}

// ---------------- apply BN + ReLU (layer 1) ----------------
__global__ void apply_relu_kernel(int M) {
    int i = blockIdx.x * blockDim.x + threadIdx.x;
    if (i >= M * (D / 4)) return;
    int c4 = i & (D / 4 - 1);
    float4 v = ((const float4*)g_h)[i];
    float4 sc = *(const float4*)&g_stats[2 * D + c4 * 4];
    float4 sh = *(const float4*)&g_stats[3 * D + c4 * 4];
    float4 o;
    o.x = fmaxf(fmaf(v.x, sc.x, sh.x), 0.f);
    o.y = fmaxf(fmaf(v.y, sc.y, sh.y), 0.f);
    o.z = fmaxf(fmaf(v.z, sc.z, sh.z), 0.f);
    o.w = fmaxf(fmaf(v.w, sc.w, sh.w), 0.f);
    ((float4*)g_h1)[i] = o;
}

// ---------------- apply BN + residual + ReLU (layer 2) ----------------
__global__ void final_kernel(const float* __restrict__ xin, float* __restrict__ out, int M) {
    int i = blockIdx.x * blockDim.x + threadIdx.x;
    if (i >= M * (D / 4)) return;
    int c4 = i & (D / 4 - 1);
    float4 v = ((const float4*)g_h)[i];
    float4 xv = ((const float4*)xin)[i];
    float4 sc = *(const float4*)&g_stats[2 * D + c4 * 4];
    float4 sh = *(const float4*)&g_stats[3 * D + c4 * 4];
    float4 o;
    o.x = fmaxf(fmaf(v.x, sc.x, sh.x) + xv.x, 0.f);
    o.y = fmaxf(fmaf(v.y, sc.y, sh.y) + xv.y, 0.f);
    o.z = fmaxf(fmaf(v.z, sc.z, sh.z) + xv.z, 0.f);
    o.w = fmaxf(fmaf(v.w, sc.w, sh.w) + xv.w, 0.f);
    ((float4*)out)[i] = o;
}

extern "C" void kernel_launch(void* const* d_in, const int* in_sizes, int n_in,
                              void* d_out, int out_size) {
    const float* x       = (const float*)d_in[0];
    const int*   ei      = (const int*)d_in[1];   // int32 edge_index
    const float* W1l     = (const float*)d_in[2];
    const float* b1      = (const float*)d_in[3];
    const float* W1r     = (const float*)d_in[4];
    const float* g1      = (const float*)d_in[5];
    const float* bt1     = (const float*)d_in[6];
    const float* W2l     = (const float*)d_in[7];
    const float* b2      = (const float*)d_in[8];
    const float* W2r     = (const float*)d_in[9];
    const float* g2      = (const float*)d_in[10];
    const float* bt2     = (const float*)d_in[11];
    float* out = (float*)d_out;

    int M = in_sizes[0] / D;
    int E = in_sizes[1] / 2;
    int eb = (E + 255) / 256;
    int nb = (M + 255) / 256;
    int nt = (M + SCAN_TILE - 1) / SCAN_TILE;   // <=64 tiles for MAXN
    int gather_blocks = (M + 7) / 8;
    int gemm_blocks = (M + 127) / 128;
    int ew_blocks = (M * (D / 4) + 255) / 256;

    // ---- CSR build (once) + weight conversion ----
    zero_cnt_kernel<<<nb, 256>>>(M);
    wt_kernel<<<128, 256>>>(W1l, W1r, W2l, W2r);
    count_kernel<<<eb, 256>>>(ei, E);
    tile_sum_kernel<<<nt, 256>>>(M);
    tile_scan_kernel<<<1, 64>>>(nt, M, E);
    local_scan_kernel<<<nt, SCAN_TILE>>>(M);
    fill_kernel<<<eb, 256>>>(ei, E);

    // ---- layer 1 ----
    zero_stats_kernel<<<1, 256>>>();
    gather_mean_kernel<<<gather_blocks, 256>>>(x, 0, M);
    gemm_mma<<<gemm_blocks, 256>>>(x, 0, 0, b1, M);
    stats_kernel<<<1, D>>>(g1, bt1, M);
    apply_relu_kernel<<<ew_blocks, 256>>>(M);

    // ---- layer 2 ----
    zero_stats_kernel<<<1, 256>>>();
    gather_mean_kernel<<<gather_blocks, 256>>>(nullptr, 1, M);
    gemm_mma<<<gemm_blocks, 256>>>(nullptr, 1, 1, b2, M);
    stats_kernel<<<1, D>>>(g2, bt2, M);
    final_kernel<<<ew_blocks, 256>>>(x, out, M);
}